// round 1
// baseline (speedup 1.0000x reference)
#include <cuda_runtime.h>

#define N_NODES 100000
#define E_EDGES 1600000
#define DIMS    3
#define C_CH    32
#define ROW_IN  67   // DIM + F
#define ROW_OUT 35   // DIM + C

// ---- scratch (static device globals; no allocation) ----
__device__ int    g_deg[N_NODES + 1];
__device__ int    g_off[N_NODES + 1];
__device__ int    g_cursor[N_NODES];
__device__ float  g_hsum[N_NODES];
__device__ float4 g_payload[E_EDGES];   // {u0,u1,u2,hsum[dst]} per CSR slot

__device__ __forceinline__ float ex2_approx(float x) {
    float r;
    asm("ex2.approx.f32 %0, %1;" : "=f"(r) : "f"(x));
    return r;
}
__device__ __forceinline__ float tanh_approx(float x) {
    float r;
    asm("tanh.approx.f32 %0, %1;" : "=f"(r) : "f"(x));
    return r;
}

// K1: one warp per node: hsum, coords->out, deg=0
__global__ void k_init(const float* __restrict__ feat, float* __restrict__ out) {
    int gtid = blockIdx.x * blockDim.x + threadIdx.x;
    int node = gtid >> 5;
    int lane = gtid & 31;
    if (node >= N_NODES) return;
    const float* row = feat + (size_t)node * ROW_IN;
    float s = row[DIMS + lane] + row[DIMS + 32 + lane];
    #pragma unroll
    for (int o = 16; o > 0; o >>= 1) s += __shfl_xor_sync(0xffffffffu, s, o);
    if (lane == 0) { g_hsum[node] = s; g_deg[node] = 0; }
    if (lane < DIMS) out[(size_t)node * ROW_OUT + lane] = row[lane];
}

// K2: histogram of src
__global__ void k_hist(const int* __restrict__ ei) {
    int e = blockIdx.x * blockDim.x + threadIdx.x;
    if (e >= E_EDGES) return;
    atomicAdd(&g_deg[ei[2 * e]], 1);
}

// K3: single-block exclusive scan -> off, cursor
__global__ void k_scan() {
    const int T = 1024;
    const int CH = (N_NODES + T - 1) / T;  // 98
    __shared__ int sh[T];
    int t = threadIdx.x;
    int base = t * CH;
    int lim = N_NODES - base;
    if (lim > CH) lim = CH;
    if (lim < 0) lim = 0;

    int sum = 0;
    for (int i = 0; i < lim; i++) sum += g_deg[base + i];
    sh[t] = sum;
    __syncthreads();
    for (int o = 1; o < T; o <<= 1) {
        int v = (t >= o) ? sh[t - o] : 0;
        __syncthreads();
        sh[t] += v;
        __syncthreads();
    }
    int run = (t == 0) ? 0 : sh[t - 1];
    for (int i = 0; i < lim; i++) {
        g_off[base + i]    = run;
        g_cursor[base + i] = run;
        run += g_deg[base + i];
    }
    if (t == T - 1) g_off[N_NODES] = sh[T - 1];
}

// K4: per-edge: u = tanh((c_dst - c_src) @ W + b); scatter payload to CSR slot
__global__ void k_scatter(const float* __restrict__ feat,
                          const int*   __restrict__ ei,
                          const float* __restrict__ w,
                          const float* __restrict__ b) {
    int e = blockIdx.x * blockDim.x + threadIdx.x;
    if (e >= E_EDGES) return;
    int src = ei[2 * e];
    int dst = ei[2 * e + 1];
    const float* cs = feat + (size_t)src * ROW_IN;
    const float* cd = feat + (size_t)dst * ROW_IN;
    float dx = cd[0] - cs[0];
    float dy = cd[1] - cs[1];
    float dz = cd[2] - cs[2];
    // w_dense is (DIM, R) row-major: w[d*3 + r]
    float u0 = tanh_approx(fmaf(dz, w[6], fmaf(dy, w[3], fmaf(dx, w[0], b[0]))));
    float u1 = tanh_approx(fmaf(dz, w[7], fmaf(dy, w[4], fmaf(dx, w[1], b[1]))));
    float u2 = tanh_approx(fmaf(dz, w[8], fmaf(dy, w[5], fmaf(dx, w[2], b[2]))));
    float hs = g_hsum[dst];
    int pos = atomicAdd(&g_cursor[src], 1);
    g_payload[pos] = make_float4(u0, u1, u2, hs);
}

// K5: one warp per node, lane = channel. Gaussian kernel weights + segment sum.
__global__ void k_main(const float* __restrict__ mu,
                       const float* __restrict__ sig,
                       float*       __restrict__ out) {
    int gtid = blockIdx.x * blockDim.x + threadIdx.x;
    int node = gtid >> 5;
    int lane = gtid & 31;    // channel
    if (node >= N_NODES) return;

    size_t bi = (size_t)lane * (size_t)N_NODES * 3 + (size_t)node * 3;
    float m0 = mu[bi + 0], m1 = mu[bi + 1], m2 = mu[bi + 2];
    // fold -0.5 * log2(e) into 1/sig so the inner loop ends in a bare ex2
    const float NHL2E = -0.7213475204444817f;
    float a0 = __fdividef(NHL2E, sig[bi + 0]);
    float a1 = __fdividef(NHL2E, sig[bi + 1]);
    float a2 = __fdividef(NHL2E, sig[bi + 2]);

    float acc = 0.0f;
    int j    = g_off[node];
    int jend = g_off[node + 1];
    for (; j < jend; j++) {
        float4 p = g_payload[j];     // broadcast across the warp
        float d0 = p.x - m0;
        float d1 = p.y - m1;
        float d2 = p.z - m2;
        float s = fmaf(d2 * d2, a2, fmaf(d1 * d1, a1, d0 * d0 * a0));
        acc = fmaf(ex2_approx(s), p.w, acc);
    }
    out[(size_t)node * ROW_OUT + DIMS + lane] = acc;
}

extern "C" void kernel_launch(void* const* d_in, const int* in_sizes, int n_in,
                              void* d_out, int out_size) {
    const float* feat = (const float*)d_in[0];
    const int*   ei   = (const int*)d_in[1];
    const float* w    = (const float*)d_in[2];
    const float* b    = (const float*)d_in[3];
    const float* mu   = (const float*)d_in[4];
    const float* sig  = (const float*)d_in[5];
    float* out = (float*)d_out;

    int blkNodeWarps = (N_NODES * 32 + 255) / 256;   // 12500
    int blkEdges     = (E_EDGES + 255) / 256;        // 6250

    k_init<<<blkNodeWarps, 256>>>(feat, out);
    k_hist<<<blkEdges, 256>>>(ei);
    k_scan<<<1, 1024>>>();
    k_scatter<<<blkEdges, 256>>>(feat, ei, w, b);
    k_main<<<blkNodeWarps, 256>>>(mu, sig, out);
}

// round 2
// speedup vs baseline: 2.0377x; 2.0377x over previous
#include <cuda_runtime.h>

#define N_NODES 100000
#define E_EDGES 1600000
#define DIMS    3
#define C_CH    32
#define ROW_IN  67   // DIM + F
#define ROW_OUT 35   // DIM + C
#define NB_SCAN 98   // ceil(N/1024)

// ---- scratch (static device globals; no allocation) ----
__device__ int    g_deg[N_NODES];
__device__ int    g_loc[N_NODES];
__device__ int    g_off[N_NODES + 1];
__device__ int    g_cursor[N_NODES];
__device__ int    g_bsum[NB_SCAN];
__device__ int    g_btop[NB_SCAN];
__device__ float4 g_ch[N_NODES];        // {x, y, z, hsum}
__device__ float4 g_payload[E_EDGES];   // {u0,u1,u2,hsum[dst]} per CSR slot

__device__ __forceinline__ float ex2_approx(float x) {
    float r;
    asm("ex2.approx.f32 %0, %1;" : "=f"(r) : "f"(x));
    return r;
}
__device__ __forceinline__ float tanh_approx(float x) {
    float r;
    asm("tanh.approx.f32 %0, %1;" : "=f"(r) : "f"(x));
    return r;
}

// K1: one warp per node: hsum, coords->out, packed {coords,hsum}, deg=0
__global__ void k_init(const float* __restrict__ feat, float* __restrict__ out) {
    int gtid = blockIdx.x * blockDim.x + threadIdx.x;
    int node = gtid >> 5;
    int lane = gtid & 31;
    if (node >= N_NODES) return;
    const float* row = feat + (size_t)node * ROW_IN;
    float s = row[DIMS + lane] + row[DIMS + 32 + lane];
    #pragma unroll
    for (int o = 16; o > 0; o >>= 1) s += __shfl_xor_sync(0xffffffffu, s, o);
    if (lane == 0) {
        g_deg[node] = 0;
        g_ch[node] = make_float4(row[0], row[1], row[2], s);
    }
    if (lane < DIMS) out[(size_t)node * ROW_OUT + lane] = row[lane];
}

// K2: histogram of src
__global__ void k_hist(const int2* __restrict__ ei) {
    int e = blockIdx.x * blockDim.x + threadIdx.x;
    if (e >= E_EDGES) return;
    atomicAdd(&g_deg[ei[e].x], 1);
}

// K3a: per-block exclusive scan (1024 elems/block), block totals
__global__ void k_scan_part() {
    __shared__ int wsum[32];
    int i = blockIdx.x * 1024 + threadIdx.x;
    int lane = threadIdx.x & 31;
    int wid  = threadIdx.x >> 5;
    int d = (i < N_NODES) ? g_deg[i] : 0;
    int x = d;
    #pragma unroll
    for (int o = 1; o < 32; o <<= 1) {
        int v = __shfl_up_sync(0xffffffffu, x, o);
        if (lane >= o) x += v;
    }
    if (lane == 31) wsum[wid] = x;
    __syncthreads();
    if (wid == 0) {
        int w = wsum[lane];
        #pragma unroll
        for (int o = 1; o < 32; o <<= 1) {
            int v = __shfl_up_sync(0xffffffffu, w, o);
            if (lane >= o) w += v;
        }
        wsum[lane] = w;
    }
    __syncthreads();
    int excl = x - d + (wid > 0 ? wsum[wid - 1] : 0);
    if (i < N_NODES) g_loc[i] = excl;
    if (threadIdx.x == 1023) g_bsum[blockIdx.x] = wsum[31];
}

// K3b: scan the 98 block sums (tiny, 1 block)
__global__ void k_scan_tops() {
    __shared__ int sh[128];
    int t = threadIdx.x;
    int v = (t < NB_SCAN) ? g_bsum[t] : 0;
    sh[t] = v;
    __syncthreads();
    #pragma unroll
    for (int o = 1; o < 128; o <<= 1) {
        int u = (t >= o) ? sh[t - o] : 0;
        __syncthreads();
        sh[t] += u;
        __syncthreads();
    }
    if (t < NB_SCAN) {
        g_btop[t] = (t == 0) ? 0 : sh[t - 1];
        if (t == NB_SCAN - 1) g_off[N_NODES] = sh[t];
    }
}

// K3c: add block prefix -> final offsets + cursors
__global__ void k_scan_add() {
    int i = blockIdx.x * 1024 + threadIdx.x;
    if (i >= N_NODES) return;
    int o = g_loc[i] + g_btop[blockIdx.x];
    g_off[i] = o;
    g_cursor[i] = o;
}

// K4: per-edge: u = tanh((c_dst - c_src) @ W + b); scatter payload to CSR slot
__global__ void k_scatter(const int2*  __restrict__ ei,
                          const float* __restrict__ w,
                          const float* __restrict__ b) {
    int e = blockIdx.x * blockDim.x + threadIdx.x;
    if (e >= E_EDGES) return;
    int2 sd = ei[e];
    float4 cs = g_ch[sd.x];
    float4 cd = g_ch[sd.y];
    float dx = cd.x - cs.x;
    float dy = cd.y - cs.y;
    float dz = cd.z - cs.z;
    // w_dense is (DIM, R) row-major: w[d*3 + r]
    float u0 = tanh_approx(fmaf(dz, w[6], fmaf(dy, w[3], fmaf(dx, w[0], b[0]))));
    float u1 = tanh_approx(fmaf(dz, w[7], fmaf(dy, w[4], fmaf(dx, w[1], b[1]))));
    float u2 = tanh_approx(fmaf(dz, w[8], fmaf(dy, w[5], fmaf(dx, w[2], b[2]))));
    int pos = atomicAdd(&g_cursor[sd.x], 1);
    g_payload[pos] = make_float4(u0, u1, u2, cd.w);
}

// K5: one warp per node, lane = channel. Gaussian kernel weights + segment sum.
__global__ void k_main(const float* __restrict__ mu,
                       const float* __restrict__ sig,
                       float*       __restrict__ out) {
    int gtid = blockIdx.x * blockDim.x + threadIdx.x;
    int node = gtid >> 5;
    int lane = gtid & 31;    // channel
    if (node >= N_NODES) return;

    size_t bi = (size_t)lane * (size_t)N_NODES * 3 + (size_t)node * 3;
    float m0 = mu[bi + 0], m1 = mu[bi + 1], m2 = mu[bi + 2];
    // fold -0.5 * log2(e) into 1/sig so the inner loop ends in a bare ex2
    const float NHL2E = -0.7213475204444817f;
    float a0 = __fdividef(NHL2E, sig[bi + 0]);
    float a1 = __fdividef(NHL2E, sig[bi + 1]);
    float a2 = __fdividef(NHL2E, sig[bi + 2]);

    float acc = 0.0f;
    int j    = g_off[node];
    int jend = g_off[node + 1];
    #pragma unroll 2
    for (; j < jend; j++) {
        float4 p = g_payload[j];     // broadcast across the warp
        float d0 = p.x - m0;
        float d1 = p.y - m1;
        float d2 = p.z - m2;
        float s = fmaf(d2 * d2, a2, fmaf(d1 * d1, a1, d0 * d0 * a0));
        acc = fmaf(ex2_approx(s), p.w, acc);
    }
    out[(size_t)node * ROW_OUT + DIMS + lane] = acc;
}

extern "C" void kernel_launch(void* const* d_in, const int* in_sizes, int n_in,
                              void* d_out, int out_size) {
    const float* feat = (const float*)d_in[0];
    const int*   ei   = (const int*)d_in[1];
    const float* w    = (const float*)d_in[2];
    const float* b    = (const float*)d_in[3];
    const float* mu   = (const float*)d_in[4];
    const float* sig  = (const float*)d_in[5];
    float* out = (float*)d_out;

    int blkNodeWarps = (N_NODES * 32 + 255) / 256;   // 12500
    int blkEdges     = (E_EDGES + 255) / 256;        // 6250

    k_init<<<blkNodeWarps, 256>>>(feat, out);
    k_hist<<<blkEdges, 256>>>((const int2*)ei);
    k_scan_part<<<NB_SCAN, 1024>>>();
    k_scan_tops<<<1, 128>>>();
    k_scan_add<<<NB_SCAN, 1024>>>();
    k_scatter<<<blkEdges, 256>>>((const int2*)ei, w, b);
    k_main<<<blkNodeWarps, 256>>>(mu, sig, out);
}